// round 10
// baseline (speedup 1.0000x reference)
#include <cuda_runtime.h>
#include <cuda_fp16.h>
#include <stdint.h>

#define NN 100000
#define DD 128
#define EE 1600000
#define NEG 0.01f
#define EPSV 1e-5f
#define SCAN_BLK 98   // ceil(100000/1024)
#define NBKT 32

// ---------------- device scratch (no allocations allowed) ----------------
__device__ __half g_h[(size_t)NN * DD];    // GEMM output pre-scaled by dinv (h')
__device__ __half g_buf[(size_t)NN * DD];  // aggregation output, fp16
__device__ int   g_cnt[NN];
__device__ int   g_off[NN + 1];            // per-block LOCAL exclusive offsets
__device__ int   g_wpos[NN];               // local write cursors
__device__ int   g_bsum[SCAN_BLK];
__device__ int   g_boff[SCAN_BLK];         // global block offsets
__device__ int   g_ssrc[EE];               // src ids grouped by dst (CSR)
__device__ float g_dinv[NN];
__device__ float g_stats[4][NBKT][DD];     // [0]=s1 [1]=ss1 [2]=s2 [3]=ss2
__device__ int   g_ctr;                    // scan1 last-block ticket
// W pre-split to fp16 hi/lo as per-thread mma-fragment records
__device__ __align__(16) uint2 g_w1hi[4096];
__device__ __align__(16) uint2 g_w1lo[4096];
__device__ __align__(16) uint2 g_w2hi[4096];
__device__ __align__(16) uint2 g_w2lo[4096];

// ---------------- helpers ----------------
__device__ __forceinline__ uint32_t packh2(__half a, __half b) {
    __half2 t = __halves2half2(a, b);
    return *(uint32_t*)&t;
}
__device__ __forceinline__ void splith2(float x, float y, uint32_t& hi, uint32_t& lo) {
    __half hx = __float2half_rn(x);
    __half hy = __float2half_rn(y);
    float rx = x - __half2float(hx);
    float ry = y - __half2float(hy);
    hi = packh2(hx, hy);
    lo = packh2(__float2half_rn(rx), __float2half_rn(ry));
}
__device__ __forceinline__ void mma16816h(float4& d, const uint32_t a0, const uint32_t a1,
                                          const uint32_t a2, const uint32_t a3,
                                          const uint32_t b0, const uint32_t b1) {
    asm volatile(
        "mma.sync.aligned.m16n8k16.row.col.f32.f16.f16.f32 "
        "{%0,%1,%2,%3}, {%4,%5,%6,%7}, {%8,%9}, {%0,%1,%2,%3};\n"
        : "+f"(d.x), "+f"(d.y), "+f"(d.z), "+f"(d.w)
        : "r"(a0), "r"(a1), "r"(a2), "r"(a3), "r"(b0), "r"(b1));
}

// ---------------- W prep: both matrices in one launch ----------------
__global__ void k_prepw(const float* __restrict__ W1, const float* __restrict__ W2) {
    int i = blockIdx.x * blockDim.x + threadIdx.x;   // 0..8191
    if (i >= 8192) return;
    const float* W = (i < 4096) ? W1 : W2;
    uint2* bhi = (i < 4096) ? g_w1hi : g_w2hi;
    uint2* blo = (i < 4096) ? g_w1lo : g_w2lo;
    int r = i & 4095;
    int lane = r & 31, rec = r >> 5;
    int kb = rec >> 4, nf = rec & 15;
    int g = lane >> 2, tig = lane & 3;
    int k0 = kb * 16 + 2 * tig;
    int n = nf * 8 + g;
    float w00 = W[(k0 + 0) * DD + n];
    float w01 = W[(k0 + 1) * DD + n];
    float w08 = W[(k0 + 8) * DD + n];
    float w09 = W[(k0 + 9) * DD + n];
    uint32_t h0, l0, h1, l1;
    splith2(w00, w01, h0, l0);
    splith2(w08, w09, h1, l1);
    bhi[r] = make_uint2(h0, h1);
    blo[r] = make_uint2(l0, l1);
}

// ---------------- graph preprocessing ----------------
__global__ void k_hist(const int* __restrict__ dst) {
    int i = blockIdx.x * blockDim.x + threadIdx.x;
    if (i < EE / 4) {
        int4 d = ((const int4*)dst)[i];
        atomicAdd(&g_cnt[d.x], 1);
        atomicAdd(&g_cnt[d.y], 1);
        atomicAdd(&g_cnt[d.z], 1);
        atomicAdd(&g_cnt[d.w], 1);
    }
}
// per-block local exclusive scan + dinv + block totals; last block scans totals
__global__ __launch_bounds__(1024) void k_scan1() {
    __shared__ int wsum[32];
    __shared__ int lastblk;
    int tid = threadIdx.x, lane = tid & 31, wid = tid >> 5;
    int i = blockIdx.x * 1024 + tid;
    int v = (i < NN) ? g_cnt[i] : 0;
    if (i < NN) g_dinv[i] = rsqrtf((float)v + 1.0f);
    int x = v;
    #pragma unroll
    for (int s = 1; s < 32; s <<= 1) {
        int t = __shfl_up_sync(0xFFFFFFFFu, x, s);
        if (lane >= s) x += t;
    }
    if (lane == 31) wsum[wid] = x;
    __syncthreads();
    if (wid == 0) {
        int y = wsum[lane];
        #pragma unroll
        for (int s = 1; s < 32; s <<= 1) {
            int t = __shfl_up_sync(0xFFFFFFFFu, y, s);
            if (lane >= s) y += t;
        }
        wsum[lane] = y;
    }
    __syncthreads();
    int incl = x + (wid > 0 ? wsum[wid - 1] : 0);
    if (i < NN) {
        int excl = incl - v;
        g_off[i] = excl;
        g_wpos[i] = excl;
    }
    if (i == NN - 1) g_off[NN] = incl;   // local inclusive total at the end
    if (tid == 1023) g_bsum[blockIdx.x] = incl;
    // last-block ticket: scan the 98 block totals in this kernel
    __threadfence();
    __syncthreads();
    if (tid == 0) lastblk = (atomicAdd(&g_ctr, 1) == SCAN_BLK - 1) ? 1 : 0;
    __syncthreads();
    if (lastblk && wid == 0) {
        int carry = 0;
        for (int base = 0; base < SCAN_BLK; base += 32) {
            int idx2 = base + lane;
            int vv = (idx2 < SCAN_BLK) ? g_bsum[idx2] : 0;
            int xx = vv;
            #pragma unroll
            for (int s = 1; s < 32; s <<= 1) {
                int t = __shfl_up_sync(0xFFFFFFFFu, xx, s);
                if (lane >= s) xx += t;
            }
            if (idx2 < SCAN_BLK) g_boff[idx2] = xx - vv + carry;
            carry += __shfl_sync(0xFFFFFFFFu, xx, 31);
        }
    }
}
// 4 edges per thread: int4 loads, 4 independent atomic/store chains (MLP)
__global__ void k_scatter(const int* __restrict__ src, const int* __restrict__ dst) {
    int i = blockIdx.x * blockDim.x + threadIdx.x;
    if (i >= EE / 4) return;
    int4 s4 = ((const int4*)src)[i];
    int4 d4 = ((const int4*)dst)[i];
    int p0 = atomicAdd(&g_wpos[d4.x], 1) + g_boff[d4.x >> 10];
    int p1 = atomicAdd(&g_wpos[d4.y], 1) + g_boff[d4.y >> 10];
    int p2 = atomicAdd(&g_wpos[d4.z], 1) + g_boff[d4.z >> 10];
    int p3 = atomicAdd(&g_wpos[d4.w], 1) + g_boff[d4.w >> 10];
    g_ssrc[p0] = s4.x;
    g_ssrc[p1] = s4.y;
    g_ssrc[p2] = s4.z;
    g_ssrc[p3] = s4.w;
}

// ---------------- GEMM layer 1: C = dinv_row * (fp16(A) @ W), fp16 out ----------
#define SMEMG (65536 + 1024)
__global__ __launch_bounds__(256, 2) void k_gemm_l1(const float* __restrict__ A,
                                                    const uint2* __restrict__ Bhi,
                                                    const uint2* __restrict__ Blo,
                                                    __half* __restrict__ C) {
    extern __shared__ unsigned char sm[];
    uint2* sWhi = (uint2*)sm;                     // 32KB
    uint2* sWlo = (uint2*)(sm + 32768);           // 32KB
    const int tid = threadIdx.x;
    #pragma unroll
    for (int i = 0; i < 16; i++) {
        sWhi[tid + i * 256] = Bhi[tid + i * 256];
        sWlo[tid + i * 256] = Blo[tid + i * 256];
    }
    __syncthreads();

    const int w = tid >> 5, lane = tid & 31;
    const int g = lane >> 2, tig = lane & 3;
    const int row0 = blockIdx.x * 128 + w * 16 + g;
    const int row8 = row0 + 8;
    const bool ok0 = row0 < NN, ok8 = row8 < NN;

    float4 acc[16];
    #pragma unroll
    for (int nf = 0; nf < 16; nf++) acc[nf] = make_float4(0.f, 0.f, 0.f, 0.f);

    for (int kb = 0; kb < 8; kb++) {
        const int c0 = kb * 16 + tig * 2;
        const int c1 = c0 + 8;
        float2 v00 = ok0 ? *(const float2*)(A + (size_t)row0 * DD + c0) : make_float2(0.f, 0.f);
        float2 v01 = ok0 ? *(const float2*)(A + (size_t)row0 * DD + c1) : make_float2(0.f, 0.f);
        float2 v10 = ok8 ? *(const float2*)(A + (size_t)row8 * DD + c0) : make_float2(0.f, 0.f);
        float2 v11 = ok8 ? *(const float2*)(A + (size_t)row8 * DD + c1) : make_float2(0.f, 0.f);
        uint32_t a0, a1, a2, a3;
        {
            __half2 t;
            t = __floats2half2_rn(v00.x, v00.y); a0 = *(uint32_t*)&t;
            t = __floats2half2_rn(v10.x, v10.y); a1 = *(uint32_t*)&t;
            t = __floats2half2_rn(v01.x, v01.y); a2 = *(uint32_t*)&t;
            t = __floats2half2_rn(v11.x, v11.y); a3 = *(uint32_t*)&t;
        }
        const uint2* bh = sWhi + (kb * 16) * 32 + lane;
        const uint2* bl = sWlo + (kb * 16) * 32 + lane;
        #pragma unroll
        for (int nf = 0; nf < 16; nf++) {
            uint2 bhv = bh[nf * 32];
            uint2 blv = bl[nf * 32];
            mma16816h(acc[nf], a0, a1, a2, a3, bhv.x, bhv.y);
            mma16816h(acc[nf], a0, a1, a2, a3, blv.x, blv.y);
        }
    }
    const float di0 = ok0 ? g_dinv[row0] : 0.f;
    const float di8 = ok8 ? g_dinv[row8] : 0.f;
    if (ok0) {
        #pragma unroll
        for (int nf = 0; nf < 16; nf++) {
            __half2 o = __floats2half2_rn(acc[nf].x * di0, acc[nf].y * di0);
            *(__half2*)(C + (size_t)row0 * DD + nf * 8 + tig * 2) = o;
        }
    }
    if (ok8) {
        #pragma unroll
        for (int nf = 0; nf < 16; nf++) {
            __half2 o = __floats2half2_rn(acc[nf].z * di8, acc[nf].w * di8);
            *(__half2*)(C + (size_t)row8 * DD + nf * 8 + tig * 2) = o;
        }
    }
}

// ---------------- GEMM layer 2: A fp16, BN1 (from fused stats) + leakyrelu -------
__global__ __launch_bounds__(256, 2) void k_gemm_l2(const __half* __restrict__ A,
                                                    const uint2* __restrict__ Bhi,
                                                    const uint2* __restrict__ Blo,
                                                    __half* __restrict__ C,
                                                    const float* __restrict__ gamma,
                                                    const float* __restrict__ beta) {
    extern __shared__ unsigned char sm[];
    uint2* sWhi = (uint2*)sm;
    uint2* sWlo = (uint2*)(sm + 32768);
    float* sSc = (float*)(sm + 65536);
    float* sSh = (float*)(sm + 66048);
    const int tid = threadIdx.x;
    #pragma unroll
    for (int i = 0; i < 16; i++) {
        sWhi[tid + i * 256] = Bhi[tid + i * 256];
        sWlo[tid + i * 256] = Blo[tid + i * 256];
    }
    if (tid < 128) {
        float s = 0.f, ss = 0.f;
        #pragma unroll
        for (int b = 0; b < NBKT; b++) {
            s += g_stats[0][b][tid];
            ss += g_stats[1][b][tid];
        }
        float mean = s * (1.0f / NN);
        float var = ss * (1.0f / NN) - mean * mean;
        float r = rsqrtf(var + EPSV);
        float sc = r * gamma[tid];
        sSc[tid] = sc;
        sSh[tid] = fmaf(-mean, sc, beta[tid]);
    }
    __syncthreads();

    const int w = tid >> 5, lane = tid & 31;
    const int g = lane >> 2, tig = lane & 3;
    const int row0 = blockIdx.x * 128 + w * 16 + g;
    const int row8 = row0 + 8;
    const bool ok0 = row0 < NN, ok8 = row8 < NN;
    const uint32_t* __restrict__ Ah2 = (const uint32_t*)A;   // half2 view

    float4 acc[16];
    #pragma unroll
    for (int nf = 0; nf < 16; nf++) acc[nf] = make_float4(0.f, 0.f, 0.f, 0.f);

    for (int kb = 0; kb < 8; kb++) {
        const int c0 = kb * 16 + tig * 2;
        const int c1 = c0 + 8;
        uint32_t r00 = ok0 ? Ah2[(size_t)row0 * 64 + (c0 >> 1)] : 0u;
        uint32_t r01 = ok0 ? Ah2[(size_t)row0 * 64 + (c1 >> 1)] : 0u;
        uint32_t r10 = ok8 ? Ah2[(size_t)row8 * 64 + (c0 >> 1)] : 0u;
        uint32_t r11 = ok8 ? Ah2[(size_t)row8 * 64 + (c1 >> 1)] : 0u;
        float2 sc0 = *(const float2*)&sSc[c0], sh0 = *(const float2*)&sSh[c0];
        float2 sc1 = *(const float2*)&sSc[c1], sh1 = *(const float2*)&sSh[c1];
        uint32_t a0, a1, a2, a3;
        {
            float2 f; float y0, y1; __half2 t;
            f = __half22float2(*(__half2*)&r00);
            y0 = fmaf(f.x, sc0.x, sh0.x); y0 = y0 > 0.f ? y0 : NEG * y0;
            y1 = fmaf(f.y, sc0.y, sh0.y); y1 = y1 > 0.f ? y1 : NEG * y1;
            t = __floats2half2_rn(y0, y1); a0 = *(uint32_t*)&t;
            f = __half22float2(*(__half2*)&r10);
            y0 = fmaf(f.x, sc0.x, sh0.x); y0 = y0 > 0.f ? y0 : NEG * y0;
            y1 = fmaf(f.y, sc0.y, sh0.y); y1 = y1 > 0.f ? y1 : NEG * y1;
            t = __floats2half2_rn(y0, y1); a1 = *(uint32_t*)&t;
            f = __half22float2(*(__half2*)&r01);
            y0 = fmaf(f.x, sc1.x, sh1.x); y0 = y0 > 0.f ? y0 : NEG * y0;
            y1 = fmaf(f.y, sc1.y, sh1.y); y1 = y1 > 0.f ? y1 : NEG * y1;
            t = __floats2half2_rn(y0, y1); a2 = *(uint32_t*)&t;
            f = __half22float2(*(__half2*)&r11);
            y0 = fmaf(f.x, sc1.x, sh1.x); y0 = y0 > 0.f ? y0 : NEG * y0;
            y1 = fmaf(f.y, sc1.y, sh1.y); y1 = y1 > 0.f ? y1 : NEG * y1;
            t = __floats2half2_rn(y0, y1); a3 = *(uint32_t*)&t;
        }
        const uint2* bh = sWhi + (kb * 16) * 32 + lane;
        const uint2* bl = sWlo + (kb * 16) * 32 + lane;
        #pragma unroll
        for (int nf = 0; nf < 16; nf++) {
            uint2 bhv = bh[nf * 32];
            uint2 blv = bl[nf * 32];
            mma16816h(acc[nf], a0, a1, a2, a3, bhv.x, bhv.y);
            mma16816h(acc[nf], a0, a1, a2, a3, blv.x, blv.y);
        }
    }
    const float di0 = ok0 ? g_dinv[row0] : 0.f;
    const float di8 = ok8 ? g_dinv[row8] : 0.f;
    if (ok0) {
        #pragma unroll
        for (int nf = 0; nf < 16; nf++) {
            __half2 o = __floats2half2_rn(acc[nf].x * di0, acc[nf].y * di0);
            *(__half2*)(C + (size_t)row0 * DD + nf * 8 + tig * 2) = o;
        }
    }
    if (ok8) {
        #pragma unroll
        for (int nf = 0; nf < 16; nf++) {
            __half2 o = __floats2half2_rn(acc[nf].z * di8, acc[nf].w * di8);
            *(__half2*)(C + (size_t)row8 * DD + nf * 8 + tig * 2) = o;
        }
    }
}

// ---------------- per-node CSR aggregation + fused BN stats --------------
// h pre-scaled by dinv -> weightless gather+add; 16-deep gather batches,
// dual accumulators to halve the dependent-FADD chain.
#define GSTEP(vv) \
    { float2 f0 = __half22float2(*(__half2*)&(vv).x); \
      float2 f1 = __half22float2(*(__half2*)&(vv).y); \
      accA.x += f0.x; accA.y += f0.y; accA.z += f1.x; accA.w += f1.y; }
#define GSTEP2(vv) \
    { float2 f0 = __half22float2(*(__half2*)&(vv).x); \
      float2 f1 = __half22float2(*(__half2*)&(vv).y); \
      accB.x += f0.x; accB.y += f0.y; accB.z += f1.x; accB.w += f1.y; }
__global__ __launch_bounds__(256) void k_agg(const __half* __restrict__ h,
                                             __half* __restrict__ agg, int layer) {
    __shared__ float rs[8][DD];
    __shared__ float rss[8][DD];
    int node = blockIdx.x * 8 + (threadIdx.x >> 5);
    int q = threadIdx.x >> 5;
    int lane = threadIdx.x & 31;
    const uint2* __restrict__ hp = (const uint2*)h;   // 4 halves per lane
    float di = g_dinv[node];
    uint2 sv = hp[(size_t)node * 32 + lane];          // self (already dinv-scaled)
    float2 a01 = __half22float2(*(__half2*)&sv.x);
    float2 a23 = __half22float2(*(__half2*)&sv.y);
    float4 accA = make_float4(a01.x, a01.y, a23.x, a23.y);
    float4 accB = make_float4(0.f, 0.f, 0.f, 0.f);
    int e0 = g_off[node] + g_boff[node >> 10];
    int e1 = g_off[node + 1] + g_boff[(node + 1) >> 10];
    for (int base = e0; base < e1; base += 32) {
        int t = base + lane;
        int idx = (t < e1) ? g_ssrc[t] : 0;           // one coalesced LDG per 32 edges
        int cnt = min(32, e1 - base);
        int j = 0;
        for (; j + 16 <= cnt; j += 16) {
            int s0 = __shfl_sync(0xFFFFFFFFu, idx, j);
            int s1 = __shfl_sync(0xFFFFFFFFu, idx, j + 1);
            int s2 = __shfl_sync(0xFFFFFFFFu, idx, j + 2);
            int s3 = __shfl_sync(0xFFFFFFFFu, idx, j + 3);
            int s4 = __shfl_sync(0xFFFFFFFFu, idx, j + 4);
            int s5 = __shfl_sync(0xFFFFFFFFu, idx, j + 5);
            int s6 = __shfl_sync(0xFFFFFFFFu, idx, j + 6);
            int s7 = __shfl_sync(0xFFFFFFFFu, idx, j + 7);
            int s8 = __shfl_sync(0xFFFFFFFFu, idx, j + 8);
            int s9 = __shfl_sync(0xFFFFFFFFu, idx, j + 9);
            int sa = __shfl_sync(0xFFFFFFFFu, idx, j + 10);
            int sb = __shfl_sync(0xFFFFFFFFu, idx, j + 11);
            int sc = __shfl_sync(0xFFFFFFFFu, idx, j + 12);
            int sd = __shfl_sync(0xFFFFFFFFu, idx, j + 13);
            int se = __shfl_sync(0xFFFFFFFFu, idx, j + 14);
            int sf = __shfl_sync(0xFFFFFFFFu, idx, j + 15);
            uint2 v0 = hp[(size_t)s0 * 32 + lane];
            uint2 v1 = hp[(size_t)s1 * 32 + lane];
            uint2 v2 = hp[(size_t)s2 * 32 + lane];
            uint2 v3 = hp[(size_t)s3 * 32 + lane];
            uint2 v4 = hp[(size_t)s4 * 32 + lane];
            uint2 v5 = hp[(size_t)s5 * 32 + lane];
            uint2 v6 = hp[(size_t)s6 * 32 + lane];
            uint2 v7 = hp[(size_t)s7 * 32 + lane];
            uint2 v8 = hp[(size_t)s8 * 32 + lane];
            uint2 v9 = hp[(size_t)s9 * 32 + lane];
            uint2 va = hp[(size_t)sa * 32 + lane];
            uint2 vb = hp[(size_t)sb * 32 + lane];
            uint2 vc = hp[(size_t)sc * 32 + lane];
            uint2 vd = hp[(size_t)sd * 32 + lane];
            uint2 ve = hp[(size_t)se * 32 + lane];
            uint2 vf = hp[(size_t)sf * 32 + lane];
            GSTEP(v0) GSTEP2(v1) GSTEP(v2) GSTEP2(v3)
            GSTEP(v4) GSTEP2(v5) GSTEP(v6) GSTEP2(v7)
            GSTEP(v8) GSTEP2(v9) GSTEP(va) GSTEP2(vb)
            GSTEP(vc) GSTEP2(vd) GSTEP(ve) GSTEP2(vf)
        }
        for (; j + 4 <= cnt; j += 4) {
            int s0 = __shfl_sync(0xFFFFFFFFu, idx, j);
            int s1 = __shfl_sync(0xFFFFFFFFu, idx, j + 1);
            int s2 = __shfl_sync(0xFFFFFFFFu, idx, j + 2);
            int s3 = __shfl_sync(0xFFFFFFFFu, idx, j + 3);
            uint2 v0 = hp[(size_t)s0 * 32 + lane];
            uint2 v1 = hp[(size_t)s1 * 32 + lane];
            uint2 v2 = hp[(size_t)s2 * 32 + lane];
            uint2 v3 = hp[(size_t)s3 * 32 + lane];
            GSTEP(v0) GSTEP2(v1) GSTEP(v2) GSTEP2(v3)
        }
        for (; j < cnt; j++) {
            int s = __shfl_sync(0xFFFFFFFFu, idx, j);
            uint2 v = hp[(size_t)s * 32 + lane];
            GSTEP(v)
        }
    }
    float4 acc = make_float4((accA.x + accB.x) * di, (accA.y + accB.y) * di,
                             (accA.z + accB.z) * di, (accA.w + accB.w) * di);
    __half2 o01 = __floats2half2_rn(acc.x, acc.y);
    __half2 o23 = __floats2half2_rn(acc.z, acc.w);
    ((uint2*)agg)[(size_t)node * 32 + lane] = make_uint2(*(uint32_t*)&o01, *(uint32_t*)&o23);

    // fused BN statistics: block reduction over the 8 nodes, atomic into buckets
    rs[q][lane * 4 + 0] = acc.x; rs[q][lane * 4 + 1] = acc.y;
    rs[q][lane * 4 + 2] = acc.z; rs[q][lane * 4 + 3] = acc.w;
    rss[q][lane * 4 + 0] = acc.x * acc.x; rss[q][lane * 4 + 1] = acc.y * acc.y;
    rss[q][lane * 4 + 2] = acc.z * acc.z; rss[q][lane * 4 + 3] = acc.w * acc.w;
    __syncthreads();
    int tid = threadIdx.x;
    if (tid < DD) {
        float s = 0.f, ss = 0.f;
        #pragma unroll
        for (int k = 0; k < 8; k++) {
            s += rs[k][tid];
            ss += rss[k][tid];
        }
        int bucket = blockIdx.x & (NBKT - 1);
        atomicAdd(&g_stats[2 * layer + 0][bucket][tid], s);
        atomicAdd(&g_stats[2 * layer + 1][bucket][tid], ss);
    }
}

// ---------------- final: BN2 (from fused stats) + residual + leakyrelu ----------
__global__ __launch_bounds__(256) void k_final(const __half* __restrict__ agg,
                                               const float* __restrict__ x,
                                               float* __restrict__ out,
                                               const float* __restrict__ gamma,
                                               const float* __restrict__ beta) {
    __shared__ float sSc[DD];
    __shared__ float sSh[DD];
    int tid = threadIdx.x;
    if (tid < DD) {
        float s = 0.f, ss = 0.f;
        #pragma unroll
        for (int b = 0; b < NBKT; b++) {
            s += g_stats[2][b][tid];
            ss += g_stats[3][b][tid];
        }
        float mean = s * (1.0f / NN);
        float var = ss * (1.0f / NN) - mean * mean;
        float r = rsqrtf(var + EPSV);
        float sc = r * gamma[tid];
        sSc[tid] = sc;
        sSh[tid] = fmaf(-mean, sc, beta[tid]);
    }
    __syncthreads();
    int i = blockIdx.x * blockDim.x + tid;
    if (i >= NN * DD / 4) return;
    int c = (i & 31) * 4;
    uint2 u = ((const uint2*)agg)[i];
    float2 v01 = __half22float2(*(__half2*)&u.x);
    float2 v23 = __half22float2(*(__half2*)&u.y);
    float4 xr = ((const float4*)x)[i];
    float4 o;
    float y;
    y = fmaf(v01.x, sSc[c + 0], sSh[c + 0]) + xr.x; o.x = y > 0.f ? y : NEG * y;
    y = fmaf(v01.y, sSc[c + 1], sSh[c + 1]) + xr.y; o.y = y > 0.f ? y : NEG * y;
    y = fmaf(v23.x, sSc[c + 2], sSh[c + 2]) + xr.z; o.z = y > 0.f ? y : NEG * y;
    y = fmaf(v23.y, sSc[c + 3], sSh[c + 3]) + xr.w; o.w = y > 0.f ? y : NEG * y;
    ((float4*)out)[i] = o;
}

// ---------------- launch ----------------
extern "C" void kernel_launch(void* const* d_in, const int* in_sizes, int n_in,
                              void* d_out, int out_size) {
    const float* x   = (const float*)d_in[0];
    const int*   ei  = (const int*)d_in[1];
    const int*   src = ei;
    const int*   dst = ei + EE;
    const float* W1  = (const float*)d_in[2];
    // b1 = d_in[3]: cancels inside BatchNorm
    const float* g1  = (const float*)d_in[4];
    const float* be1 = (const float*)d_in[5];
    const float* W2  = (const float*)d_in[6];
    // b2 = d_in[7]: cancels likewise
    const float* g2  = (const float*)d_in[8];
    const float* be2 = (const float*)d_in[9];
    float* out = (float*)d_out;

    __half* p_h = nullptr;
    __half* p_buf = nullptr;
    int* p_cnt = nullptr;
    float* p_stats = nullptr;
    int* p_ctr = nullptr;
    uint2 *p_w1hi, *p_w1lo, *p_w2hi, *p_w2lo;
    cudaGetSymbolAddress((void**)&p_h, g_h);
    cudaGetSymbolAddress((void**)&p_buf, g_buf);
    cudaGetSymbolAddress((void**)&p_cnt, g_cnt);
    cudaGetSymbolAddress((void**)&p_stats, g_stats);
    cudaGetSymbolAddress((void**)&p_ctr, g_ctr);
    cudaGetSymbolAddress((void**)&p_w1hi, g_w1hi);
    cudaGetSymbolAddress((void**)&p_w1lo, g_w1lo);
    cudaGetSymbolAddress((void**)&p_w2hi, g_w2hi);
    cudaGetSymbolAddress((void**)&p_w2lo, g_w2lo);

    cudaFuncSetAttribute(k_gemm_l1, cudaFuncAttributeMaxDynamicSharedMemorySize, SMEMG);
    cudaFuncSetAttribute(k_gemm_l2, cudaFuncAttributeMaxDynamicSharedMemorySize, SMEMG);

    // second stream + events for fork-join (host-side; fall back if creation fails)
    cudaStream_t s2 = 0;
    bool forked = (cudaStreamCreateWithFlags(&s2, cudaStreamNonBlocking) == cudaSuccess);
    cudaEvent_t eFork = 0, eDinv = 0, eGemm = 0;
    if (forked) forked = (cudaEventCreateWithFlags(&eFork, cudaEventDisableTiming) == cudaSuccess);
    if (forked) forked = (cudaEventCreateWithFlags(&eDinv, cudaEventDisableTiming) == cudaSuccess);
    if (forked) forked = (cudaEventCreateWithFlags(&eGemm, cudaEventDisableTiming) == cudaSuccess);
    cudaStream_t sG = forked ? s2 : (cudaStream_t)0;

    // default stream: edge preprocessing. s2: weight prep + stats memset + GEMM1.
    cudaMemsetAsync(p_cnt, 0, NN * sizeof(int), 0);
    cudaMemsetAsync(p_ctr, 0, sizeof(int), 0);
    if (forked) {
        cudaEventRecord(eFork, 0);
        cudaStreamWaitEvent(s2, eFork, 0);
    }
    cudaMemsetAsync(p_stats, 0, sizeof(float) * 4 * NBKT * DD, sG);
    k_prepw<<<32, 256, 0, sG>>>(W1, W2);
    k_hist<<<(EE / 4 + 255) / 256, 256>>>(dst);
    k_scan1<<<SCAN_BLK, 1024>>>();
    if (forked) {
        cudaEventRecord(eDinv, 0);
        cudaStreamWaitEvent(s2, eDinv, 0);
    }
    k_scatter<<<(EE / 4 + 255) / 256, 256>>>(src, dst);
    k_gemm_l1<<<(NN + 127) / 128, 256, SMEMG, sG>>>(x, p_w1hi, p_w1lo, p_h);
    if (forked) {
        cudaEventRecord(eGemm, s2);
        cudaStreamWaitEvent(0, eGemm, 0);   // join: agg needs scatter AND gemm1
    }

    // layer 1: aggregation with fused BN stats
    k_agg<<<NN / 8, 256>>>(p_h, p_buf, 0);

    // layer 2: GEMM (BN1 from stats + act fused), agg (fused stats), final
    k_gemm_l2<<<(NN + 127) / 128, 256, SMEMG>>>(p_buf, p_w2hi, p_w2lo, p_h, g1, be1);
    k_agg<<<NN / 8, 256>>>(p_h, p_buf, 1);
    k_final<<<(NN * DD / 4 + 255) / 256, 256>>>(p_buf, x, out, g2, be2);
}

// round 14
// speedup vs baseline: 1.0811x; 1.0811x over previous
#include <cuda_runtime.h>
#include <cuda_fp16.h>
#include <stdint.h>

#define NN 100000
#define DD 128
#define EE 1600000
#define NEG 0.01f
#define EPSV 1e-5f
#define SCAN_BLK 98   // ceil(100000/1024)

// ---------------- device scratch (no allocations allowed) ----------------
__device__ __half g_h[(size_t)NN * DD];    // GEMM output pre-scaled by dinv (h')
__device__ __half g_buf[(size_t)NN * DD];  // aggregation output, fp16
__device__ int   g_cnt[NN];
__device__ int   g_off[NN + 1];            // per-block LOCAL exclusive offsets
__device__ int   g_wpos[NN];               // local write cursors
__device__ int   g_bsum[SCAN_BLK];
__device__ int   g_boff[SCAN_BLK];         // global block offsets
__device__ int   g_ssrc[EE];               // src ids grouped by dst (CSR)
__device__ float g_dinv[NN];
__device__ float g_stats[4][8][DD];        // [0]=s1 [1]=ss1 [2]=s2 [3]=ss2, 8 buckets
__device__ int   g_ctr;                    // scan1 last-block ticket
// W pre-split to fp16 hi/lo as per-thread mma-fragment records
__device__ __align__(16) uint2 g_w1hi[4096];
__device__ __align__(16) uint2 g_w1lo[4096];
__device__ __align__(16) uint2 g_w2hi[4096];
__device__ __align__(16) uint2 g_w2lo[4096];

// ---------------- helpers ----------------
__device__ __forceinline__ uint32_t packh2(__half a, __half b) {
    __half2 t = __halves2half2(a, b);
    return *(uint32_t*)&t;
}
__device__ __forceinline__ void splith2(float x, float y, uint32_t& hi, uint32_t& lo) {
    __half hx = __float2half_rn(x);
    __half hy = __float2half_rn(y);
    float rx = x - __half2float(hx);
    float ry = y - __half2float(hy);
    hi = packh2(hx, hy);
    lo = packh2(__float2half_rn(rx), __float2half_rn(ry));
}
__device__ __forceinline__ void mma16816h(float4& d, const uint32_t a0, const uint32_t a1,
                                          const uint32_t a2, const uint32_t a3,
                                          const uint32_t b0, const uint32_t b1) {
    asm volatile(
        "mma.sync.aligned.m16n8k16.row.col.f32.f16.f16.f32 "
        "{%0,%1,%2,%3}, {%4,%5,%6,%7}, {%8,%9}, {%0,%1,%2,%3};\n"
        : "+f"(d.x), "+f"(d.y), "+f"(d.z), "+f"(d.w)
        : "r"(a0), "r"(a1), "r"(a2), "r"(a3), "r"(b0), "r"(b1));
}

// ---------------- W prep: both matrices in one launch ----------------
__global__ void k_prepw(const float* __restrict__ W1, const float* __restrict__ W2) {
    int i = blockIdx.x * blockDim.x + threadIdx.x;   // 0..8191
    if (i >= 8192) return;
    const float* W = (i < 4096) ? W1 : W2;
    uint2* bhi = (i < 4096) ? g_w1hi : g_w2hi;
    uint2* blo = (i < 4096) ? g_w1lo : g_w2lo;
    int r = i & 4095;
    int lane = r & 31, rec = r >> 5;
    int kb = rec >> 4, nf = rec & 15;
    int g = lane >> 2, tig = lane & 3;
    int k0 = kb * 16 + 2 * tig;
    int n = nf * 8 + g;
    float w00 = W[(k0 + 0) * DD + n];
    float w01 = W[(k0 + 1) * DD + n];
    float w08 = W[(k0 + 8) * DD + n];
    float w09 = W[(k0 + 9) * DD + n];
    uint32_t h0, l0, h1, l1;
    splith2(w00, w01, h0, l0);
    splith2(w08, w09, h1, l1);
    bhi[r] = make_uint2(h0, h1);
    blo[r] = make_uint2(l0, l1);
}

// ---------------- graph preprocessing ----------------
__global__ void k_hist(const int* __restrict__ dst) {
    int i = blockIdx.x * blockDim.x + threadIdx.x;
    if (i < EE / 4) {
        int4 d = ((const int4*)dst)[i];
        atomicAdd(&g_cnt[d.x], 1);
        atomicAdd(&g_cnt[d.y], 1);
        atomicAdd(&g_cnt[d.z], 1);
        atomicAdd(&g_cnt[d.w], 1);
    }
}
// per-block local exclusive scan + dinv + block totals; last block scans totals
__global__ __launch_bounds__(1024) void k_scan1() {
    __shared__ int wsum[32];
    __shared__ int lastblk;
    int tid = threadIdx.x, lane = tid & 31, wid = tid >> 5;
    int i = blockIdx.x * 1024 + tid;
    int v = (i < NN) ? g_cnt[i] : 0;
    if (i < NN) g_dinv[i] = rsqrtf((float)v + 1.0f);
    int x = v;
    #pragma unroll
    for (int s = 1; s < 32; s <<= 1) {
        int t = __shfl_up_sync(0xFFFFFFFFu, x, s);
        if (lane >= s) x += t;
    }
    if (lane == 31) wsum[wid] = x;
    __syncthreads();
    if (wid == 0) {
        int y = wsum[lane];
        #pragma unroll
        for (int s = 1; s < 32; s <<= 1) {
            int t = __shfl_up_sync(0xFFFFFFFFu, y, s);
            if (lane >= s) y += t;
        }
        wsum[lane] = y;
    }
    __syncthreads();
    int incl = x + (wid > 0 ? wsum[wid - 1] : 0);
    if (i < NN) {
        int excl = incl - v;
        g_off[i] = excl;
        g_wpos[i] = excl;
    }
    if (i == NN - 1) g_off[NN] = incl;   // local inclusive total at the end
    if (tid == 1023) g_bsum[blockIdx.x] = incl;
    // last-block ticket: scan the 98 block totals in this kernel
    __threadfence();
    __syncthreads();
    if (tid == 0) lastblk = (atomicAdd(&g_ctr, 1) == SCAN_BLK - 1) ? 1 : 0;
    __syncthreads();
    if (lastblk && wid == 0) {
        int carry = 0;
        for (int base = 0; base < SCAN_BLK; base += 32) {
            int idx2 = base + lane;
            int vv = (idx2 < SCAN_BLK) ? g_bsum[idx2] : 0;
            int xx = vv;
            #pragma unroll
            for (int s = 1; s < 32; s <<= 1) {
                int t = __shfl_up_sync(0xFFFFFFFFu, xx, s);
                if (lane >= s) xx += t;
            }
            if (idx2 < SCAN_BLK) g_boff[idx2] = xx - vv + carry;
            carry += __shfl_sync(0xFFFFFFFFu, xx, 31);
        }
    }
}
// 4 edges per thread: int4 loads, 4 independent atomic/store chains
__global__ void k_scatter(const int* __restrict__ src, const int* __restrict__ dst) {
    int i = blockIdx.x * blockDim.x + threadIdx.x;
    if (i >= EE / 4) return;
    int4 s4 = ((const int4*)src)[i];
    int4 d4 = ((const int4*)dst)[i];
    int p0 = atomicAdd(&g_wpos[d4.x], 1) + g_boff[d4.x >> 10];
    int p1 = atomicAdd(&g_wpos[d4.y], 1) + g_boff[d4.y >> 10];
    int p2 = atomicAdd(&g_wpos[d4.z], 1) + g_boff[d4.z >> 10];
    int p3 = atomicAdd(&g_wpos[d4.w], 1) + g_boff[d4.w >> 10];
    g_ssrc[p0] = s4.x;
    g_ssrc[p1] = s4.y;
    g_ssrc[p2] = s4.z;
    g_ssrc[p3] = s4.w;
}

// ---------------- GEMM layer 1: C = dinv_row * (fp16(A) @ W), fp16 out ----------
#define SMEMG (65536 + 1024)
__global__ __launch_bounds__(256, 2) void k_gemm_l1(const float* __restrict__ A,
                                                    const uint2* __restrict__ Bhi,
                                                    const uint2* __restrict__ Blo,
                                                    __half* __restrict__ C) {
    extern __shared__ unsigned char sm[];
    uint2* sWhi = (uint2*)sm;                     // 32KB
    uint2* sWlo = (uint2*)(sm + 32768);           // 32KB
    const int tid = threadIdx.x;
    #pragma unroll
    for (int i = 0; i < 16; i++) {
        sWhi[tid + i * 256] = Bhi[tid + i * 256];
        sWlo[tid + i * 256] = Blo[tid + i * 256];
    }
    __syncthreads();

    const int w = tid >> 5, lane = tid & 31;
    const int g = lane >> 2, tig = lane & 3;
    const int row0 = blockIdx.x * 128 + w * 16 + g;
    const int row8 = row0 + 8;
    const bool ok0 = row0 < NN, ok8 = row8 < NN;

    float4 acc[16];
    #pragma unroll
    for (int nf = 0; nf < 16; nf++) acc[nf] = make_float4(0.f, 0.f, 0.f, 0.f);

    for (int kb = 0; kb < 8; kb++) {
        const int c0 = kb * 16 + tig * 2;
        const int c1 = c0 + 8;
        float2 v00 = ok0 ? *(const float2*)(A + (size_t)row0 * DD + c0) : make_float2(0.f, 0.f);
        float2 v01 = ok0 ? *(const float2*)(A + (size_t)row0 * DD + c1) : make_float2(0.f, 0.f);
        float2 v10 = ok8 ? *(const float2*)(A + (size_t)row8 * DD + c0) : make_float2(0.f, 0.f);
        float2 v11 = ok8 ? *(const float2*)(A + (size_t)row8 * DD + c1) : make_float2(0.f, 0.f);
        uint32_t a0, a1, a2, a3;
        {
            __half2 t;
            t = __floats2half2_rn(v00.x, v00.y); a0 = *(uint32_t*)&t;
            t = __floats2half2_rn(v10.x, v10.y); a1 = *(uint32_t*)&t;
            t = __floats2half2_rn(v01.x, v01.y); a2 = *(uint32_t*)&t;
            t = __floats2half2_rn(v11.x, v11.y); a3 = *(uint32_t*)&t;
        }
        const uint2* bh = sWhi + (kb * 16) * 32 + lane;
        const uint2* bl = sWlo + (kb * 16) * 32 + lane;
        #pragma unroll
        for (int nf = 0; nf < 16; nf++) {
            uint2 bhv = bh[nf * 32];
            uint2 blv = bl[nf * 32];
            mma16816h(acc[nf], a0, a1, a2, a3, bhv.x, bhv.y);
            mma16816h(acc[nf], a0, a1, a2, a3, blv.x, blv.y);
        }
    }
    const float di0 = ok0 ? g_dinv[row0] : 0.f;
    const float di8 = ok8 ? g_dinv[row8] : 0.f;
    if (ok0) {
        #pragma unroll
        for (int nf = 0; nf < 16; nf++) {
            __half2 o = __floats2half2_rn(acc[nf].x * di0, acc[nf].y * di0);
            *(__half2*)(C + (size_t)row0 * DD + nf * 8 + tig * 2) = o;
        }
    }
    if (ok8) {
        #pragma unroll
        for (int nf = 0; nf < 16; nf++) {
            __half2 o = __floats2half2_rn(acc[nf].z * di8, acc[nf].w * di8);
            *(__half2*)(C + (size_t)row8 * DD + nf * 8 + tig * 2) = o;
        }
    }
}

// ---------------- GEMM layer 2: A fp16, BN1 (from fused stats) + leakyrelu -------
__global__ __launch_bounds__(256, 2) void k_gemm_l2(const __half* __restrict__ A,
                                                    const uint2* __restrict__ Bhi,
                                                    const uint2* __restrict__ Blo,
                                                    __half* __restrict__ C,
                                                    const float* __restrict__ gamma,
                                                    const float* __restrict__ beta) {
    extern __shared__ unsigned char sm[];
    uint2* sWhi = (uint2*)sm;
    uint2* sWlo = (uint2*)(sm + 32768);
    float* sSc = (float*)(sm + 65536);
    float* sSh = (float*)(sm + 66048);
    const int tid = threadIdx.x;
    #pragma unroll
    for (int i = 0; i < 16; i++) {
        sWhi[tid + i * 256] = Bhi[tid + i * 256];
        sWlo[tid + i * 256] = Blo[tid + i * 256];
    }
    if (tid < 128) {
        float s = 0.f, ss = 0.f;
        #pragma unroll
        for (int b = 0; b < 8; b++) {
            s += g_stats[0][b][tid];
            ss += g_stats[1][b][tid];
        }
        float mean = s * (1.0f / NN);
        float var = ss * (1.0f / NN) - mean * mean;
        float r = rsqrtf(var + EPSV);
        float sc = r * gamma[tid];
        sSc[tid] = sc;
        sSh[tid] = fmaf(-mean, sc, beta[tid]);
    }
    __syncthreads();

    const int w = tid >> 5, lane = tid & 31;
    const int g = lane >> 2, tig = lane & 3;
    const int row0 = blockIdx.x * 128 + w * 16 + g;
    const int row8 = row0 + 8;
    const bool ok0 = row0 < NN, ok8 = row8 < NN;
    const uint32_t* __restrict__ Ah2 = (const uint32_t*)A;   // half2 view

    float4 acc[16];
    #pragma unroll
    for (int nf = 0; nf < 16; nf++) acc[nf] = make_float4(0.f, 0.f, 0.f, 0.f);

    for (int kb = 0; kb < 8; kb++) {
        const int c0 = kb * 16 + tig * 2;
        const int c1 = c0 + 8;
        uint32_t r00 = ok0 ? Ah2[(size_t)row0 * 64 + (c0 >> 1)] : 0u;
        uint32_t r01 = ok0 ? Ah2[(size_t)row0 * 64 + (c1 >> 1)] : 0u;
        uint32_t r10 = ok8 ? Ah2[(size_t)row8 * 64 + (c0 >> 1)] : 0u;
        uint32_t r11 = ok8 ? Ah2[(size_t)row8 * 64 + (c1 >> 1)] : 0u;
        float2 sc0 = *(const float2*)&sSc[c0], sh0 = *(const float2*)&sSh[c0];
        float2 sc1 = *(const float2*)&sSc[c1], sh1 = *(const float2*)&sSh[c1];
        uint32_t a0, a1, a2, a3;
        {
            float2 f; float y0, y1; __half2 t;
            f = __half22float2(*(__half2*)&r00);
            y0 = fmaf(f.x, sc0.x, sh0.x); y0 = y0 > 0.f ? y0 : NEG * y0;
            y1 = fmaf(f.y, sc0.y, sh0.y); y1 = y1 > 0.f ? y1 : NEG * y1;
            t = __floats2half2_rn(y0, y1); a0 = *(uint32_t*)&t;
            f = __half22float2(*(__half2*)&r10);
            y0 = fmaf(f.x, sc0.x, sh0.x); y0 = y0 > 0.f ? y0 : NEG * y0;
            y1 = fmaf(f.y, sc0.y, sh0.y); y1 = y1 > 0.f ? y1 : NEG * y1;
            t = __floats2half2_rn(y0, y1); a1 = *(uint32_t*)&t;
            f = __half22float2(*(__half2*)&r01);
            y0 = fmaf(f.x, sc1.x, sh1.x); y0 = y0 > 0.f ? y0 : NEG * y0;
            y1 = fmaf(f.y, sc1.y, sh1.y); y1 = y1 > 0.f ? y1 : NEG * y1;
            t = __floats2half2_rn(y0, y1); a2 = *(uint32_t*)&t;
            f = __half22float2(*(__half2*)&r11);
            y0 = fmaf(f.x, sc1.x, sh1.x); y0 = y0 > 0.f ? y0 : NEG * y0;
            y1 = fmaf(f.y, sc1.y, sh1.y); y1 = y1 > 0.f ? y1 : NEG * y1;
            t = __floats2half2_rn(y0, y1); a3 = *(uint32_t*)&t;
        }
        const uint2* bh = sWhi + (kb * 16) * 32 + lane;
        const uint2* bl = sWlo + (kb * 16) * 32 + lane;
        #pragma unroll
        for (int nf = 0; nf < 16; nf++) {
            uint2 bhv = bh[nf * 32];
            uint2 blv = bl[nf * 32];
            mma16816h(acc[nf], a0, a1, a2, a3, bhv.x, bhv.y);
            mma16816h(acc[nf], a0, a1, a2, a3, blv.x, blv.y);
        }
    }
    const float di0 = ok0 ? g_dinv[row0] : 0.f;
    const float di8 = ok8 ? g_dinv[row8] : 0.f;
    if (ok0) {
        #pragma unroll
        for (int nf = 0; nf < 16; nf++) {
            __half2 o = __floats2half2_rn(acc[nf].x * di0, acc[nf].y * di0);
            *(__half2*)(C + (size_t)row0 * DD + nf * 8 + tig * 2) = o;
        }
    }
    if (ok8) {
        #pragma unroll
        for (int nf = 0; nf < 16; nf++) {
            __half2 o = __floats2half2_rn(acc[nf].z * di8, acc[nf].w * di8);
            *(__half2*)(C + (size_t)row8 * DD + nf * 8 + tig * 2) = o;
        }
    }
}

// ---------------- per-node CSR aggregation + fused BN stats --------------
// h pre-scaled by dinv -> weightless gather+add. Grid = exactly NN/8 blocks.
__global__ __launch_bounds__(256) void k_agg(const __half* __restrict__ h,
                                             __half* __restrict__ agg, int layer) {
    __shared__ float rs[8][DD];
    __shared__ float rss[8][DD];
    int node = blockIdx.x * 8 + (threadIdx.x >> 5);
    int q = threadIdx.x >> 5;
    int lane = threadIdx.x & 31;
    const uint2* __restrict__ hp = (const uint2*)h;   // 4 halves per lane
    float di = g_dinv[node];
    uint2 sv = hp[(size_t)node * 32 + lane];          // self (already dinv-scaled)
    float2 a01 = __half22float2(*(__half2*)&sv.x);
    float2 a23 = __half22float2(*(__half2*)&sv.y);
    float4 acc = make_float4(a01.x, a01.y, a23.x, a23.y);
    int e0 = g_off[node] + g_boff[node >> 10];
    int e1 = g_off[node + 1] + g_boff[(node + 1) >> 10];
    for (int base = e0; base < e1; base += 32) {
        int t = base + lane;
        int idx = (t < e1) ? g_ssrc[t] : 0;           // one coalesced LDG per 32 edges
        int cnt = min(32, e1 - base);
        int j = 0;
        for (; j + 8 <= cnt; j += 8) {
            int s0 = __shfl_sync(0xFFFFFFFFu, idx, j);
            int s1 = __shfl_sync(0xFFFFFFFFu, idx, j + 1);
            int s2 = __shfl_sync(0xFFFFFFFFu, idx, j + 2);
            int s3 = __shfl_sync(0xFFFFFFFFu, idx, j + 3);
            int s4 = __shfl_sync(0xFFFFFFFFu, idx, j + 4);
            int s5 = __shfl_sync(0xFFFFFFFFu, idx, j + 5);
            int s6 = __shfl_sync(0xFFFFFFFFu, idx, j + 6);
            int s7 = __shfl_sync(0xFFFFFFFFu, idx, j + 7);
            uint2 v0 = hp[(size_t)s0 * 32 + lane];
            uint2 v1 = hp[(size_t)s1 * 32 + lane];
            uint2 v2 = hp[(size_t)s2 * 32 + lane];
            uint2 v3 = hp[(size_t)s3 * 32 + lane];
            uint2 v4 = hp[(size_t)s4 * 32 + lane];
            uint2 v5 = hp[(size_t)s5 * 32 + lane];
            uint2 v6 = hp[(size_t)s6 * 32 + lane];
            uint2 v7 = hp[(size_t)s7 * 32 + lane];
            float2 f;
            f = __half22float2(*(__half2*)&v0.x); acc.x += f.x; acc.y += f.y;
            f = __half22float2(*(__half2*)&v0.y); acc.z += f.x; acc.w += f.y;
            f = __half22float2(*(__half2*)&v1.x); acc.x += f.x; acc.y += f.y;
            f = __half22float2(*(__half2*)&v1.y); acc.z += f.x; acc.w += f.y;
            f = __half22float2(*(__half2*)&v2.x); acc.x += f.x; acc.y += f.y;
            f = __half22float2(*(__half2*)&v2.y); acc.z += f.x; acc.w += f.y;
            f = __half22float2(*(__half2*)&v3.x); acc.x += f.x; acc.y += f.y;
            f = __half22float2(*(__half2*)&v3.y); acc.z += f.x; acc.w += f.y;
            f = __half22float2(*(__half2*)&v4.x); acc.x += f.x; acc.y += f.y;
            f = __half22float2(*(__half2*)&v4.y); acc.z += f.x; acc.w += f.y;
            f = __half22float2(*(__half2*)&v5.x); acc.x += f.x; acc.y += f.y;
            f = __half22float2(*(__half2*)&v5.y); acc.z += f.x; acc.w += f.y;
            f = __half22float2(*(__half2*)&v6.x); acc.x += f.x; acc.y += f.y;
            f = __half22float2(*(__half2*)&v6.y); acc.z += f.x; acc.w += f.y;
            f = __half22float2(*(__half2*)&v7.x); acc.x += f.x; acc.y += f.y;
            f = __half22float2(*(__half2*)&v7.y); acc.z += f.x; acc.w += f.y;
        }
        for (; j < cnt; j++) {
            int s = __shfl_sync(0xFFFFFFFFu, idx, j);
            uint2 v = hp[(size_t)s * 32 + lane];
            float2 f;
            f = __half22float2(*(__half2*)&v.x); acc.x += f.x; acc.y += f.y;
            f = __half22float2(*(__half2*)&v.y); acc.z += f.x; acc.w += f.y;
        }
    }
    acc.x *= di; acc.y *= di; acc.z *= di; acc.w *= di;
    __half2 o01 = __floats2half2_rn(acc.x, acc.y);
    __half2 o23 = __floats2half2_rn(acc.z, acc.w);
    ((uint2*)agg)[(size_t)node * 32 + lane] = make_uint2(*(uint32_t*)&o01, *(uint32_t*)&o23);

    // fused BN statistics: block reduction over the 8 nodes, atomic into buckets
    rs[q][lane * 4 + 0] = acc.x; rs[q][lane * 4 + 1] = acc.y;
    rs[q][lane * 4 + 2] = acc.z; rs[q][lane * 4 + 3] = acc.w;
    rss[q][lane * 4 + 0] = acc.x * acc.x; rss[q][lane * 4 + 1] = acc.y * acc.y;
    rss[q][lane * 4 + 2] = acc.z * acc.z; rss[q][lane * 4 + 3] = acc.w * acc.w;
    __syncthreads();
    int tid = threadIdx.x;
    if (tid < DD) {
        float s = 0.f, ss = 0.f;
        #pragma unroll
        for (int k = 0; k < 8; k++) {
            s += rs[k][tid];
            ss += rss[k][tid];
        }
        int bucket = blockIdx.x & 7;
        atomicAdd(&g_stats[2 * layer + 0][bucket][tid], s);
        atomicAdd(&g_stats[2 * layer + 1][bucket][tid], ss);
    }
}

// ---------------- final: BN2 (from fused stats) + residual + leakyrelu ----------
__global__ __launch_bounds__(256) void k_final(const __half* __restrict__ agg,
                                               const float* __restrict__ x,
                                               float* __restrict__ out,
                                               const float* __restrict__ gamma,
                                               const float* __restrict__ beta) {
    __shared__ float sSc[DD];
    __shared__ float sSh[DD];
    int tid = threadIdx.x;
    if (tid < DD) {
        float s = 0.f, ss = 0.f;
        #pragma unroll
        for (int b = 0; b < 8; b++) {
            s += g_stats[2][b][tid];
            ss += g_stats[3][b][tid];
        }
        float mean = s * (1.0f / NN);
        float var = ss * (1.0f / NN) - mean * mean;
        float r = rsqrtf(var + EPSV);
        float sc = r * gamma[tid];
        sSc[tid] = sc;
        sSh[tid] = fmaf(-mean, sc, beta[tid]);
    }
    __syncthreads();
    int i = blockIdx.x * blockDim.x + tid;
    if (i >= NN * DD / 4) return;
    int c = (i & 31) * 4;
    uint2 u = ((const uint2*)agg)[i];
    float2 v01 = __half22float2(*(__half2*)&u.x);
    float2 v23 = __half22float2(*(__half2*)&u.y);
    float4 xr = ((const float4*)x)[i];
    float4 o;
    float y;
    y = fmaf(v01.x, sSc[c + 0], sSh[c + 0]) + xr.x; o.x = y > 0.f ? y : NEG * y;
    y = fmaf(v01.y, sSc[c + 1], sSh[c + 1]) + xr.y; o.y = y > 0.f ? y : NEG * y;
    y = fmaf(v23.x, sSc[c + 2], sSh[c + 2]) + xr.z; o.z = y > 0.f ? y : NEG * y;
    y = fmaf(v23.y, sSc[c + 3], sSh[c + 3]) + xr.w; o.w = y > 0.f ? y : NEG * y;
    ((float4*)out)[i] = o;
}

// ---------------- launch ----------------
extern "C" void kernel_launch(void* const* d_in, const int* in_sizes, int n_in,
                              void* d_out, int out_size) {
    const float* x   = (const float*)d_in[0];
    const int*   ei  = (const int*)d_in[1];
    const int*   src = ei;
    const int*   dst = ei + EE;
    const float* W1  = (const float*)d_in[2];
    // b1 = d_in[3]: cancels inside BatchNorm
    const float* g1  = (const float*)d_in[4];
    const float* be1 = (const float*)d_in[5];
    const float* W2  = (const float*)d_in[6];
    // b2 = d_in[7]: cancels likewise
    const float* g2  = (const float*)d_in[8];
    const float* be2 = (const float*)d_in[9];
    float* out = (float*)d_out;

    __half* p_h = nullptr;
    __half* p_buf = nullptr;
    int* p_cnt = nullptr;
    float* p_stats = nullptr;
    int* p_ctr = nullptr;
    uint2 *p_w1hi, *p_w1lo, *p_w2hi, *p_w2lo;
    cudaGetSymbolAddress((void**)&p_h, g_h);
    cudaGetSymbolAddress((void**)&p_buf, g_buf);
    cudaGetSymbolAddress((void**)&p_cnt, g_cnt);
    cudaGetSymbolAddress((void**)&p_stats, g_stats);
    cudaGetSymbolAddress((void**)&p_ctr, g_ctr);
    cudaGetSymbolAddress((void**)&p_w1hi, g_w1hi);
    cudaGetSymbolAddress((void**)&p_w1lo, g_w1lo);
    cudaGetSymbolAddress((void**)&p_w2hi, g_w2hi);
    cudaGetSymbolAddress((void**)&p_w2lo, g_w2lo);

    cudaFuncSetAttribute(k_gemm_l1, cudaFuncAttributeMaxDynamicSharedMemorySize, SMEMG);
    cudaFuncSetAttribute(k_gemm_l2, cudaFuncAttributeMaxDynamicSharedMemorySize, SMEMG);

    // second stream + events for fork-join (host-side; fall back if creation fails)
    cudaStream_t s2 = 0;
    bool forked = (cudaStreamCreateWithFlags(&s2, cudaStreamNonBlocking) == cudaSuccess);
    cudaEvent_t eFork = 0, eDinv = 0, eGemm = 0;
    if (forked) forked = (cudaEventCreateWithFlags(&eFork, cudaEventDisableTiming) == cudaSuccess);
    if (forked) forked = (cudaEventCreateWithFlags(&eDinv, cudaEventDisableTiming) == cudaSuccess);
    if (forked) forked = (cudaEventCreateWithFlags(&eGemm, cudaEventDisableTiming) == cudaSuccess);
    cudaStream_t sG = forked ? s2 : (cudaStream_t)0;

    // default stream: edge preprocessing. s2: weight prep + GEMM1 (needs dinv).
    cudaMemsetAsync(p_cnt, 0, NN * sizeof(int), 0);
    cudaMemsetAsync(p_stats, 0, sizeof(float) * 4 * 8 * DD, 0);
    cudaMemsetAsync(p_ctr, 0, sizeof(int), 0);
    if (forked) {
        cudaEventRecord(eFork, 0);
        cudaStreamWaitEvent(s2, eFork, 0);
    }
    k_prepw<<<32, 256, 0, sG>>>(W1, W2);
    k_hist<<<(EE / 4 + 255) / 256, 256>>>(dst);
    k_scan1<<<SCAN_BLK, 1024>>>();
    if (forked) {
        cudaEventRecord(eDinv, 0);
        cudaStreamWaitEvent(s2, eDinv, 0);
    }
    k_scatter<<<(EE / 4 + 255) / 256, 256>>>(src, dst);
    k_gemm_l1<<<(NN + 127) / 128, 256, SMEMG, sG>>>(x, p_w1hi, p_w1lo, p_h);
    if (forked) {
        cudaEventRecord(eGemm, s2);
        cudaStreamWaitEvent(0, eGemm, 0);   // join: agg needs scatter AND gemm1
    }

    // layer 1: aggregation with fused BN stats
    k_agg<<<NN / 8, 256>>>(p_h, p_buf, 0);

    // layer 2: GEMM (BN1 from stats + act fused), agg (fused stats), final
    k_gemm_l2<<<(NN + 127) / 128, 256, SMEMG>>>(p_buf, p_w2hi, p_w2lo, p_h, g1, be1);
    k_agg<<<NN / 8, 256>>>(p_h, p_buf, 1);
    k_final<<<(NN * DD / 4 + 255) / 256, 256>>>(p_buf, x, out, g2, be2);
}